// round 1
// baseline (speedup 1.0000x reference)
#include <cuda_runtime.h>

// out[i] = Param_b[b_params[i]] + sum_{e: w_rows[e]==i} Param_W[w_params[e]] * x[w_cols[e]]
// N = 262144, E = 16777216, NPARAMS = 1280, NB = 16

#define NPARAMS 1280

__global__ void bias_init_kernel(float* __restrict__ out,
                                 const float* __restrict__ Param_b,
                                 const int* __restrict__ b_params,
                                 int n) {
    int i = blockIdx.x * blockDim.x + threadIdx.x;
    if (i < n) {
        out[i] = __ldg(&Param_b[__ldg(&b_params[i])]);
    }
}

__global__ __launch_bounds__(256) void edge_scatter_kernel(
    float* __restrict__ out,
    const float* __restrict__ x,
    const float* __restrict__ Param_W,
    const int4* __restrict__ rows4,
    const int4* __restrict__ cols4,
    const int4* __restrict__ params4,
    int e4)  // E/4
{
    __shared__ float sW[NPARAMS];
    // cooperative load of Param_W into shared (1280 floats, 256 threads -> 5 each)
    #pragma unroll
    for (int i = threadIdx.x; i < NPARAMS; i += 256) {
        sW[i] = Param_W[i];
    }
    __syncthreads();

    int idx = blockIdx.x * blockDim.x + threadIdx.x;
    if (idx >= e4) return;

    // 128-bit loads of the three index streams
    int4 r = __ldg(&rows4[idx]);
    int4 c = __ldg(&cols4[idx]);
    int4 p = __ldg(&params4[idx]);

    // issue all x gathers first for MLP
    float x0 = __ldg(&x[c.x]);
    float x1 = __ldg(&x[c.y]);
    float x2 = __ldg(&x[c.z]);
    float x3 = __ldg(&x[c.w]);

    float w0 = sW[p.x];
    float w1 = sW[p.y];
    float w2 = sW[p.z];
    float w3 = sW[p.w];

    atomicAdd(&out[r.x], w0 * x0);
    atomicAdd(&out[r.y], w1 * x1);
    atomicAdd(&out[r.z], w2 * x2);
    atomicAdd(&out[r.w], w3 * x3);
}

extern "C" void kernel_launch(void* const* d_in, const int* in_sizes, int n_in,
                              void* d_out, int out_size) {
    const float* x       = (const float*)d_in[0];
    const float* Param_W = (const float*)d_in[1];
    const float* Param_b = (const float*)d_in[2];
    const int*   w_rows  = (const int*)d_in[3];
    const int*   w_cols  = (const int*)d_in[4];
    const int*   w_params= (const int*)d_in[5];
    const int*   b_params= (const int*)d_in[6];
    float* out = (float*)d_out;

    int N = out_size;              // 262144
    int E = in_sizes[3];           // 16777216

    // 1) bias init (also overwrites 0xAA poison)
    {
        int threads = 256;
        int blocks = (N + threads - 1) / threads;
        bias_init_kernel<<<blocks, threads>>>(out, Param_b, b_params, N);
    }

    // 2) edge scatter, 4 edges per thread
    {
        int e4 = E / 4;  // E is a multiple of 4 (16777216)
        int threads = 256;
        int blocks = (e4 + threads - 1) / threads;
        edge_scatter_kernel<<<blocks, threads>>>(
            out, x, Param_W,
            (const int4*)w_rows, (const int4*)w_cols, (const int4*)w_params,
            e4);
    }
}

// round 3
// speedup vs baseline: 1.0123x; 1.0123x over previous
#include <cuda_runtime.h>

// out[i] = Param_b[b_params[i]] + sum_{e: w_rows[e]==i} Param_W[w_params[e]] * x[w_cols[e]]
// N = 262144, E = 16777216, NPARAMS = 1280, NB = 16

#define NPARAMS 1280

__global__ void bias_init_kernel(float4* __restrict__ out,
                                 const float* __restrict__ Param_b,
                                 const int4* __restrict__ b_params,
                                 int n4) {
    int i = blockIdx.x * blockDim.x + threadIdx.x;
    if (i < n4) {
        int4 b = __ldcs(&b_params[i]);
        float4 v;
        v.x = __ldg(&Param_b[b.x]);
        v.y = __ldg(&Param_b[b.y]);
        v.z = __ldg(&Param_b[b.z]);
        v.w = __ldg(&Param_b[b.w]);
        out[i] = v;
    }
}

__global__ __launch_bounds__(256) void edge_scatter_kernel(
    float* __restrict__ out,
    const float* __restrict__ x,
    const float* __restrict__ Param_W,
    const int4* __restrict__ rows4,
    const int4* __restrict__ cols4,
    const int4* __restrict__ params4,
    int e4)  // E/4
{
    __shared__ float sW[NPARAMS];
    #pragma unroll
    for (int i = threadIdx.x; i < NPARAMS; i += 256) {
        sW[i] = Param_W[i];
    }
    __syncthreads();

    int idx = blockIdx.x * blockDim.x + threadIdx.x;
    if (idx >= e4) return;

    // Streaming (evict-first) loads for the one-touch index streams so they
    // don't evict x from L1/L2. x gathers use default (L1-allocating) loads.
    int4 r = __ldcs(&rows4[idx]);
    int4 c = __ldcs(&cols4[idx]);
    int4 p = __ldcs(&params4[idx]);

    // issue all x gathers first for MLP
    float x0 = __ldg(&x[c.x]);
    float x1 = __ldg(&x[c.y]);
    float x2 = __ldg(&x[c.z]);
    float x3 = __ldg(&x[c.w]);

    float w0 = sW[p.x];
    float w1 = sW[p.y];
    float w2 = sW[p.z];
    float w3 = sW[p.w];

    atomicAdd(&out[r.x], w0 * x0);
    atomicAdd(&out[r.y], w1 * x1);
    atomicAdd(&out[r.z], w2 * x2);
    atomicAdd(&out[r.w], w3 * x3);
}

extern "C" void kernel_launch(void* const* d_in, const int* in_sizes, int n_in,
                              void* d_out, int out_size) {
    const float* x       = (const float*)d_in[0];
    const float* Param_W = (const float*)d_in[1];
    const float* Param_b = (const float*)d_in[2];
    const int*   w_rows  = (const int*)d_in[3];
    const int*   w_cols  = (const int*)d_in[4];
    const int*   w_params= (const int*)d_in[5];
    const int*   b_params= (const int*)d_in[6];
    float* out = (float*)d_out;

    int N = out_size;              // 262144
    int E = in_sizes[3];           // 16777216

    // 1) bias init (also overwrites 0xAA poison), vectorized x4
    {
        int n4 = N / 4;
        int threads = 256;
        int blocks = (n4 + threads - 1) / threads;
        bias_init_kernel<<<blocks, threads>>>((float4*)out, Param_b,
                                              (const int4*)b_params, n4);
    }

    // 2) edge scatter, 4 edges per thread
    {
        int e4 = E / 4;  // E is a multiple of 4 (16777216)
        int threads = 256;
        int blocks = (e4 + threads - 1) / threads;
        edge_scatter_kernel<<<blocks, threads>>>(
            out, x, Param_W,
            (const int4*)w_rows, (const int4*)w_cols, (const int4*)w_params,
            e4);
    }
}